// round 7
// baseline (speedup 1.0000x reference)
#include <cuda_runtime.h>
#include <stdint.h>

// B=128, N=256, T=1024, C=10
#define T_LEN   1024
#define N_NEUR  256
#define C_GAP   10
#define WPB     8
#define THREADS (WPB * 32)
#define RPW     4                         // rows per warp
#define STAGES  3
#define TOTAL_ROWS (128 * 256)
#define GRID    (TOTAL_ROWS / (WPB * RPW))     // 1024
#define ROWSTEP (GRID * WPB)                   // 8192
#define NEGINF  (-3.402823466e38f)
#define FULL    0xffffffffu
#define MAXCL   96
#define SMEM_DYN (WPB * STAGES * T_LEN * 4)    // 96 KB

__device__ float    g_loss;
__device__ unsigned g_tick;

extern __shared__ float dynbuf[];

__device__ __forceinline__ void prefetch_row(const float* __restrict__ vmem,
                                             unsigned dst_u32, int row, int l) {
    const float4* src = (const float4*)(vmem + (size_t)row * T_LEN);
    #pragma unroll
    for (int k = 0; k < 8; ++k) {
        unsigned sa = dst_u32 + (unsigned)((k * 32 + l) * 16);
        asm volatile("cp.async.cg.shared.global [%0], [%1], 16;"
                     :: "r"(sa), "l"(src + k * 32 + l) : "memory");
    }
    asm volatile("cp.async.commit_group;" ::: "memory");
}

// Process one row resident at smem addr sbase (4KB). Returns loss contribution.
__device__ __forceinline__ float process_row(unsigned sbase, int row, int l,
                                             unsigned* shb, unsigned* shcl,
                                             const int* __restrict__ labels,
                                             float* __restrict__ out) {
    const bool lane0 = (l == 0);
    float maxall = NEGINF;
    const int shift = 4 * (l & 7);
    const int grp   = l >> 3;
    #pragma unroll
    for (int k = 0; k < 8; ++k) {
        float4 v;
        unsigned a = sbase + (unsigned)((k * 32 + l) * 16);
        asm volatile("ld.shared.v4.f32 {%0,%1,%2,%3}, [%4];"
                     : "=f"(v.x), "=f"(v.y), "=f"(v.z), "=f"(v.w) : "r"(a));
        maxall = fmaxf(maxall, fmaxf(fmaxf(v.x, v.y), fmaxf(v.z, v.w)));
        unsigned nib = (v.x >= 0.0f ? 1u : 0u)
                     | (v.y >= 0.0f ? 2u : 0u)
                     | (v.z >= 0.0f ? 4u : 0u)
                     | (v.w >= 0.0f ? 8u : 0u);
        unsigned word = nib << shift;
        word |= __shfl_xor_sync(FULL, word, 1);
        word |= __shfl_xor_sync(FULL, word, 2);
        word |= __shfl_xor_sync(FULL, word, 4);   // 8-lane group holds window mask
        if ((l & 7) == 0) shb[4 * k + grp] = word;
    }
    __syncwarp();
    unsigned m = shb[l];                 // spike mask of window [32l, 32l+32)

    // cluster-start mask: spike with no spike in previous C steps
    unsigned prev = __shfl_up_sync(FULL, m, 1);
    if (lane0) prev = 0;
    unsigned long long A  = ((unsigned long long)m << 32) | prev;
    unsigned long long t1 = (A << 1) | (A << 2);
    unsigned long long t2 = t1 | (t1 << 2);
    unsigned long long t3 = t2 | (t2 << 4);
    unsigned long long sp = t3 | (t1 << 8);           // shifts {1..10}
    unsigned starts = m & ~(unsigned)(sp >> 32);

    const int sc = __popc(starts);
    const int nc = __reduce_add_sync(FULL, sc);

    const int b_     = row >> 8;
    const int nn     = row & (N_NEUR - 1);
    const int target = (__ldg(labels + b_) == nn) ? 1 : 0;

    float contrib = 0.0f;
    if (nc > target) {                       // warp-uniform
        if (nc == 1) {
            #pragma unroll
            for (int d = 16; d > 0; d >>= 1)
                maxall = fmaxf(maxall, __shfl_xor_sync(FULL, maxall, d));
            contrib = maxall;                // single cluster: span max == row max
        } else {
            const int pc = __popc(m);
            int ipc = pc, isc = sc;
            #pragma unroll
            for (int d = 1; d < 32; d <<= 1) {
                int vp = __shfl_up_sync(FULL, ipc, d);
                int vs = __shfl_up_sync(FULL, isc, d);
                if (l >= d) { ipc += vp; isc += vs; }
            }
            const int excl  = ipc - pc;
            int c           = isc - sc;
            const int S_tot = __shfl_sync(FULL, ipc, 31);

            unsigned sm_ = starts;
            const int tb = l * 32;
            while (sm_) {
                int bit = __ffs(sm_) - 1;
                sm_ &= sm_ - 1;
                int sb = excl + __popc(m & ((1u << bit) - 1u));
                shcl[c] = ((unsigned)sb << 16) | (unsigned)(tb + bit);
                ++c;
            }
            if (lane0) shcl[nc] = ((unsigned)S_tot << 16) | (unsigned)T_LEN;
            __syncwarp();

            int best = 0x7fffffff;
            for (int c0 = l; c0 < nc; c0 += 32) {
                unsigned a  = shcl[c0];
                unsigned bn = shcl[c0 + 1];
                int size = (int)(bn >> 16) - (int)(a >> 16);
                best = min(best, (size << 7) | c0);
            }
            best = __reduce_min_sync(FULL, (unsigned)best);
            const int cstar = best & 127;
            const unsigned a  = shcl[cstar];
            const unsigned bn = shcl[cstar + 1];
            const int cb  = (int)(a  & 0xffffu);
            const int ceN = (int)(bn & 0xffffu);
            const unsigned width = (unsigned)(ceN - cb);

            // span max from smem (blocks overlapping [cb, ceN))
            float smax = NEGINF;
            const int ks = cb >> 7, ke = (ceN - 1) >> 7;
            for (int k = ks; k <= ke; ++k) {
                float4 v;
                unsigned aa = sbase + (unsigned)((k * 32 + l) * 16);
                asm volatile("ld.shared.v4.f32 {%0,%1,%2,%3}, [%4];"
                             : "=f"(v.x), "=f"(v.y), "=f"(v.z), "=f"(v.w) : "r"(aa));
                int t0 = k * 128 + 4 * l;
                if ((unsigned)(t0     - cb) < width) smax = fmaxf(smax, v.x);
                if ((unsigned)(t0 + 1 - cb) < width) smax = fmaxf(smax, v.y);
                if ((unsigned)(t0 + 2 - cb) < width) smax = fmaxf(smax, v.z);
                if ((unsigned)(t0 + 3 - cb) < width) smax = fmaxf(smax, v.w);
            }
            #pragma unroll
            for (int d = 16; d > 0; d >>= 1)
                smax = fmaxf(smax, __shfl_xor_sync(FULL, smax, d));
            contrib = smax;
        }
    } else if (nc == 0 && target) {
        #pragma unroll
        for (int d = 16; d > 0; d >>= 1)
            maxall = fmaxf(maxall, __shfl_xor_sync(FULL, maxall, d));
        contrib = -maxall;
    }

    if (lane0) out[1 + row] = (float)nc;     // spike_output
    return contrib;
}

__global__ __launch_bounds__(THREADS)
void stca_main(const float* __restrict__ vmem,
               const int*   __restrict__ labels,
               float*       __restrict__ out)
{
    __shared__ unsigned sh_b[WPB][32];
    __shared__ unsigned sh_cl[WPB][MAXCL];
    __shared__ float    warp_contrib[WPB];

    const int tid = threadIdx.x;
    const int w   = tid >> 5;
    const int l   = tid & 31;

    unsigned wbase;
    {
        float* wbuf = dynbuf + (size_t)w * STAGES * T_LEN;
        wbase = (unsigned)__cvta_generic_to_shared(wbuf);
    }
    const int row0 = blockIdx.x * WPB + w;

    // 3-stage pipeline over 4 rows: rows row0 + i*ROWSTEP
    prefetch_row(vmem, wbase + 0 * T_LEN * 4, row0 + 0 * ROWSTEP, l);
    prefetch_row(vmem, wbase + 1 * T_LEN * 4, row0 + 1 * ROWSTEP, l);
    prefetch_row(vmem, wbase + 2 * T_LEN * 4, row0 + 2 * ROWSTEP, l);

    float lsum = 0.0f;

    asm volatile("cp.async.wait_group 2;" ::: "memory");
    lsum += process_row(wbase + 0 * T_LEN * 4, row0 + 0 * ROWSTEP, l, sh_b[w], sh_cl[w], labels, out);
    prefetch_row(vmem, wbase + 0 * T_LEN * 4, row0 + 3 * ROWSTEP, l);   // stage 3%3=0

    asm volatile("cp.async.wait_group 2;" ::: "memory");
    lsum += process_row(wbase + 1 * T_LEN * 4, row0 + 1 * ROWSTEP, l, sh_b[w], sh_cl[w], labels, out);

    asm volatile("cp.async.wait_group 1;" ::: "memory");
    lsum += process_row(wbase + 2 * T_LEN * 4, row0 + 2 * ROWSTEP, l, sh_b[w], sh_cl[w], labels, out);

    asm volatile("cp.async.wait_group 0;" ::: "memory");
    lsum += process_row(wbase + 0 * T_LEN * 4, row0 + 3 * ROWSTEP, l, sh_b[w], sh_cl[w], labels, out);

    if (l == 0) warp_contrib[w] = lsum;
    __syncthreads();

    // grid reduction: device accumulator + ticket (graph-replay safe)
    if (tid == 0) {
        float s = 0.0f;
        #pragma unroll
        for (int i = 0; i < WPB; ++i) s += warp_contrib[i];
        atomicAdd(&g_loss, s);
        __threadfence();
        unsigned t = atomicAdd(&g_tick, 1u);
        if (t == gridDim.x - 1) {            // last block: publish + reset
            __threadfence();
            out[0] = g_loss;
            g_loss = 0.0f;
            g_tick = 0u;
        }
    }
}

extern "C" void kernel_launch(void* const* d_in, const int* in_sizes, int n_in,
                              void* d_out, int out_size) {
    const float* vmem   = (const float*)d_in[0];   // [128,256,1024] f32
    // d_in[1] = vlastmem — unused by the reference forward; deliberately not read
    const int*   labels = (const int*)d_in[2];     // [128] i32
    float*       out    = (float*)d_out;           // [1 + 128*256] f32

    static bool attr_set = false;                  // host-side only; not device state
    if (!attr_set) {
        cudaFuncSetAttribute(stca_main, cudaFuncAttributeMaxDynamicSharedMemorySize, SMEM_DYN);
        attr_set = true;
    }
    stca_main<<<GRID, THREADS, SMEM_DYN>>>(vmem, labels, out);
}

// round 8
// speedup vs baseline: 1.1146x; 1.1146x over previous
#include <cuda_runtime.h>
#include <stdint.h>

// B=128, N=256, T=1024, C=10
#define T_LEN   1024
#define N_NEUR  256
#define C_GAP   10
#define WPB     8
#define THREADS (WPB * 32)
#define RPW     2                          // rows per warp (independent streams)
#define TOTAL_ROWS (128 * 256)
#define GRID    (TOTAL_ROWS / (WPB * RPW))      // 2048
#define ROWHALF (TOTAL_ROWS / RPW)              // 16384
#define NEGINF  (-3.402823466e38f)
#define FULL    0xffffffffu
#define MAXCL   96

__device__ float    g_loss;     // zero-init; reset by last block each launch
__device__ unsigned g_tick;

// Everything after the spike-mask is built: cluster structure + contribution.
__device__ __forceinline__ float finish_row(unsigned m, float maxall, int row, int l,
                                            unsigned* shcl,
                                            const float* __restrict__ rp,
                                            const int*   __restrict__ labels,
                                            float*       __restrict__ out)
{
    const bool lane0 = (l == 0);

    // cluster-start mask: spike with no spike in previous C steps
    unsigned prev = __shfl_up_sync(FULL, m, 1);
    if (lane0) prev = 0;
    unsigned long long A  = ((unsigned long long)m << 32) | prev;
    unsigned long long t1 = (A << 1) | (A << 2);          // shifts {1,2}
    unsigned long long t2 = t1 | (t1 << 2);               // {1..4}
    unsigned long long t3 = t2 | (t2 << 4);               // {1..8}
    unsigned long long sp = t3 | (t1 << 8);               // {1..10}
    unsigned starts = m & ~(unsigned)(sp >> 32);

    const int sc = __popc(starts);
    const int nc = __reduce_add_sync(FULL, sc);

    const int b_     = row >> 8;
    const int nn     = row & (N_NEUR - 1);
    const int target = (__ldg(labels + b_) == nn) ? 1 : 0;

    float contrib = 0.0f;
    if (nc > target) {                       // warp-uniform
        if (nc == 1) {
            // single cluster: span max == row max (spikes >= 0, rest < 0)
            #pragma unroll
            for (int d = 16; d > 0; d >>= 1)
                maxall = fmaxf(maxall, __shfl_xor_sync(FULL, maxall, d));
            contrib = maxall;
        } else {
            // cluster table: (spikes before start, start pos)
            const int pc = __popc(m);
            int ipc = pc, isc = sc;
            #pragma unroll
            for (int d = 1; d < 32; d <<= 1) {
                int vp = __shfl_up_sync(FULL, ipc, d);
                int vs = __shfl_up_sync(FULL, isc, d);
                if (l >= d) { ipc += vp; isc += vs; }
            }
            const int excl  = ipc - pc;
            int c           = isc - sc;
            const int S_tot = __shfl_sync(FULL, ipc, 31);

            unsigned sm_ = starts;
            const int tb = l * 32;
            while (sm_) {
                int bit = __ffs(sm_) - 1;
                sm_ &= sm_ - 1;
                int sb = excl + __popc(m & ((1u << bit) - 1u));
                shcl[c] = ((unsigned)sb << 16) | (unsigned)(tb + bit);
                ++c;
            }
            if (lane0) shcl[nc] = ((unsigned)S_tot << 16) | (unsigned)T_LEN;
            __syncwarp();

            // smallest cluster, earliest on ties
            int best = 0x7fffffff;
            for (int c0 = l; c0 < nc; c0 += 32) {
                unsigned a  = shcl[c0];
                unsigned bn = shcl[c0 + 1];
                int size = (int)(bn >> 16) - (int)(a >> 16);
                best = min(best, (size << 7) | c0);
            }
            best = __reduce_min_sync(FULL, (unsigned)best);
            const int cstar = best & 127;
            const unsigned a  = shcl[cstar];
            const unsigned bn = shcl[cstar + 1];
            const int cb  = (int)(a  & 0xffffu);
            const int ceN = (int)(bn & 0xffffu);
            const unsigned width = (unsigned)(ceN - cb);

            // re-read only float4 blocks overlapping [cb, ceN) — L2 hits, rare path
            const float4* g4 = (const float4*)rp;
            float smax = NEGINF;
            const int ks = cb >> 7, ke = (ceN - 1) >> 7;
            for (int k = ks; k <= ke; ++k) {
                float4 v = __ldg(g4 + k * 32 + l);
                int t0 = k * 128 + 4 * l;
                if ((unsigned)(t0     - cb) < width) smax = fmaxf(smax, v.x);
                if ((unsigned)(t0 + 1 - cb) < width) smax = fmaxf(smax, v.y);
                if ((unsigned)(t0 + 2 - cb) < width) smax = fmaxf(smax, v.z);
                if ((unsigned)(t0 + 3 - cb) < width) smax = fmaxf(smax, v.w);
            }
            #pragma unroll
            for (int d = 16; d > 0; d >>= 1)
                smax = fmaxf(smax, __shfl_xor_sync(FULL, smax, d));
            contrib = smax;
        }
    } else if (nc == 0 && target) {
        #pragma unroll
        for (int d = 16; d > 0; d >>= 1)
            maxall = fmaxf(maxall, __shfl_xor_sync(FULL, maxall, d));
        contrib = -maxall;
    }

    if (lane0) out[1 + row] = (float)nc;     // spike_output
    return contrib;
}

__global__ __launch_bounds__(THREADS)
void stca_main(const float* __restrict__ vmem,
               const int*   __restrict__ labels,
               float*       __restrict__ out)
{
    __shared__ unsigned sh_cl[WPB][MAXCL];
    __shared__ float    warp_contrib[WPB];

    const int tid = threadIdx.x;
    const int w   = tid >> 5;
    const int l   = tid & 31;

    const int rowA = blockIdx.x * WPB + w;
    const int rowB = rowA + ROWHALF;
    const float* rpA = vmem + (size_t)rowA * T_LEN;
    const float* rpB = vmem + (size_t)rowB * T_LEN;

    // Two independent load/ballot chains interleaved -> 2x memory streams/warp.
    float maxA = NEGINF, maxB = NEGINF;
    unsigned mA = 0, mB = 0;
    #pragma unroll
    for (int k = 0; k < 32; ++k) {
        float xA = __ldcs(rpA + k * 32 + l);
        float xB = __ldcs(rpB + k * 32 + l);
        maxA = fmaxf(maxA, xA);
        maxB = fmaxf(maxB, xB);
        unsigned bA = __ballot_sync(FULL, xA >= 0.0f);
        unsigned bB = __ballot_sync(FULL, xB >= 0.0f);
        if (l == k) { mA = bA; mB = bB; }
    }

    float lsum = finish_row(mA, maxA, rowA, l, sh_cl[w], rpA, labels, out)
               + finish_row(mB, maxB, rowB, l, sh_cl[w], rpB, labels, out);

    if (l == 0) warp_contrib[w] = lsum;
    __syncthreads();

    // grid reduction: device accumulator + ticket (graph-replay safe)
    if (tid == 0) {
        float s = 0.0f;
        #pragma unroll
        for (int i = 0; i < WPB; ++i) s += warp_contrib[i];
        atomicAdd(&g_loss, s);
        __threadfence();
        unsigned t = atomicAdd(&g_tick, 1u);
        if (t == gridDim.x - 1) {            // last block: publish + reset
            __threadfence();
            out[0] = g_loss;
            g_loss = 0.0f;
            g_tick = 0u;
        }
    }
}

extern "C" void kernel_launch(void* const* d_in, const int* in_sizes, int n_in,
                              void* d_out, int out_size) {
    const float* vmem   = (const float*)d_in[0];   // [128,256,1024] f32
    // d_in[1] = vlastmem — unused by the reference forward; deliberately not read
    const int*   labels = (const int*)d_in[2];     // [128] i32
    float*       out    = (float*)d_out;           // [1 + 128*256] f32

    stca_main<<<GRID, THREADS>>>(vmem, labels, out);
}

// round 9
// speedup vs baseline: 1.3559x; 1.2164x over previous
#include <cuda_runtime.h>
#include <stdint.h>

// B=128, N=256, T=1024, C=10
#define T_LEN   1024
#define N_NEUR  256
#define C_GAP   10
#define WPB     8
#define THREADS (WPB * 32)
#define NEGINF  (-3.402823466e38f)
#define FULL    0xffffffffu
#define MAXCL   96

__device__ float    g_loss;     // zero-init; reset by last block each launch
__device__ unsigned g_tick;

__global__ __launch_bounds__(THREADS)
void stca_main(const float* __restrict__ vmem,
               const int*   __restrict__ labels,
               float*       __restrict__ out)
{
    __shared__ unsigned sh_p[WPB][32];       // per-lane packed spike bits
    __shared__ unsigned sh_cl[WPB][MAXCL];   // (spikesBefore<<16)|startPos
    __shared__ float    warp_contrib[WPB];

    const int tid = threadIdx.x;
    const int w   = tid >> 5;
    const int l   = tid & 31;
    const bool lane0 = (l == 0);
    const int row = blockIdx.x * WPB + w;
    const float* rp = vmem + (size_t)row * T_LEN;
    const float4* g4 = (const float4*)rp;

    // ---- Phase 1: sync-free load loop. LDG.128 batched x4; each lane packs
    //      spike bits of its own elements: bit (4k+j) <-> time 128k+4l+j.
    float maxall = NEGINF;
    unsigned pack = 0;
    #pragma unroll
    for (int half = 0; half < 2; ++half) {
        float4 v[4];
        #pragma unroll
        for (int k = 0; k < 4; ++k)
            v[k] = __ldg(g4 + (half * 4 + k) * 32 + l);
        #pragma unroll
        for (int k = 0; k < 4; ++k) {
            maxall = fmaxf(maxall, fmaxf(fmaxf(v[k].x, v[k].y), fmaxf(v[k].z, v[k].w)));
            unsigned nib = (v[k].x >= 0.0f ? 1u : 0u)
                         | (v[k].y >= 0.0f ? 2u : 0u)
                         | (v[k].z >= 0.0f ? 4u : 0u)
                         | (v[k].w >= 0.0f ? 8u : 0u);
            pack |= nib << (4 * (half * 4 + k));
        }
    }
    sh_p[w][l] = pack;
    __syncwarp();

    // ---- Assemble window mask for window w=l (times [32l, 32l+32)):
    //      m = OR_i ((pack[8*(l&3)+i] >> 4*(l>>2)) & 0xF) << 4i
    unsigned m = 0;
    {
        const unsigned ksh = 4 * (l >> 2);
        const unsigned* src = &sh_p[w][8 * (l & 3)];
        #pragma unroll
        for (int i = 0; i < 8; ++i)
            m |= ((src[i] >> ksh) & 0xFu) << (4 * i);
    }

    // ---- Global cluster-start mask: spike with no spike in previous C steps.
    unsigned prev = __shfl_up_sync(FULL, m, 1);
    if (lane0) prev = 0;
    unsigned long long A  = ((unsigned long long)m << 32) | prev;
    unsigned long long t1 = (A << 1) | (A << 2);          // shifts {1,2}
    unsigned long long t2 = t1 | (t1 << 2);               // {1..4}
    unsigned long long t3 = t2 | (t2 << 4);               // {1..8}
    unsigned long long sp = t3 | (t1 << 8);               // {1..10}
    unsigned starts = m & ~(unsigned)(sp >> 32);

    const int sc = __popc(starts);
    const int nc = __reduce_add_sync(FULL, sc);

    const int b_     = row >> 8;
    const int nn     = row & (N_NEUR - 1);
    const int target = (__ldg(labels + b_) == nn) ? 1 : 0;

    float contrib = 0.0f;
    if (nc > target) {                       // warp-uniform
        if (nc == 1) {
            // single cluster: span max == row max (spikes >= 0, rest < 0)
            #pragma unroll
            for (int d = 16; d > 0; d >>= 1)
                maxall = fmaxf(maxall, __shfl_xor_sync(FULL, maxall, d));
            contrib = maxall;
        } else {
            // ---- cluster table: (spikes before start, start pos)
            const int pc = __popc(m);
            int ipc = pc, isc = sc;          // inclusive scans
            #pragma unroll
            for (int d = 1; d < 32; d <<= 1) {
                int vp = __shfl_up_sync(FULL, ipc, d);
                int vs = __shfl_up_sync(FULL, isc, d);
                if (l >= d) { ipc += vp; isc += vs; }
            }
            const int excl  = ipc - pc;      // spikes before my window
            int c           = isc - sc;      // clusters before my window
            const int S_tot = __shfl_sync(FULL, ipc, 31);

            unsigned sm_ = starts;
            const int tb = l * 32;
            while (sm_) {
                int bit = __ffs(sm_) - 1;
                sm_ &= sm_ - 1;
                int sb = excl + __popc(m & ((1u << bit) - 1u));
                sh_cl[w][c] = ((unsigned)sb << 16) | (unsigned)(tb + bit);
                ++c;
            }
            if (lane0) sh_cl[w][nc] = ((unsigned)S_tot << 16) | (unsigned)T_LEN;
            __syncwarp();

            // smallest cluster, earliest on ties: min over (size<<7 | idx)
            int best = 0x7fffffff;
            for (int c0 = l; c0 < nc; c0 += 32) {
                unsigned a  = sh_cl[w][c0];
                unsigned bn = sh_cl[w][c0 + 1];
                int size = (int)(bn >> 16) - (int)(a >> 16);
                best = min(best, (size << 7) | c0);
            }
            best = __reduce_min_sync(FULL, (unsigned)best);
            const int cstar = best & 127;
            const unsigned a  = sh_cl[w][cstar];
            const unsigned bn = sh_cl[w][cstar + 1];
            const int cb  = (int)(a  & 0xffffu);
            const int ceN = (int)(bn & 0xffffu);     // exclusive end
            const unsigned width = (unsigned)(ceN - cb);

            // re-read only float4 blocks overlapping [cb, ceN) — cache hits
            float smax = NEGINF;
            const int ks = cb >> 7, ke = (ceN - 1) >> 7;
            for (int k = ks; k <= ke; ++k) {
                float4 v = __ldg(g4 + k * 32 + l);
                int t0 = k * 128 + 4 * l;
                if ((unsigned)(t0     - cb) < width) smax = fmaxf(smax, v.x);
                if ((unsigned)(t0 + 1 - cb) < width) smax = fmaxf(smax, v.y);
                if ((unsigned)(t0 + 2 - cb) < width) smax = fmaxf(smax, v.z);
                if ((unsigned)(t0 + 3 - cb) < width) smax = fmaxf(smax, v.w);
            }
            #pragma unroll
            for (int d = 16; d > 0; d >>= 1)
                smax = fmaxf(smax, __shfl_xor_sync(FULL, smax, d));
            contrib = smax;
        }
    } else if (nc == 0 && target) {
        #pragma unroll
        for (int d = 16; d > 0; d >>= 1)
            maxall = fmaxf(maxall, __shfl_xor_sync(FULL, maxall, d));
        contrib = -maxall;
    }

    if (lane0) {
        out[1 + row] = (float)nc;            // spike_output
        warp_contrib[w] = contrib;
    }
    __syncthreads();

    // ---- grid reduction: device accumulator + ticket (graph-replay safe)
    if (tid == 0) {
        float s = 0.0f;
        #pragma unroll
        for (int i = 0; i < WPB; ++i) s += warp_contrib[i];
        atomicAdd(&g_loss, s);
        __threadfence();
        unsigned t = atomicAdd(&g_tick, 1u);
        if (t == gridDim.x - 1) {            // last block: publish + reset
            __threadfence();
            out[0] = g_loss;
            g_loss = 0.0f;
            g_tick = 0u;
        }
    }
}

extern "C" void kernel_launch(void* const* d_in, const int* in_sizes, int n_in,
                              void* d_out, int out_size) {
    const float* vmem   = (const float*)d_in[0];   // [128,256,1024] f32
    // d_in[1] = vlastmem — unused by the reference forward; deliberately not read
    const int*   labels = (const int*)d_in[2];     // [128] i32
    float*       out    = (float*)d_out;           // [1 + 128*256] f32

    const int total_rows = 128 * 256;              // 32768
    stca_main<<<total_rows / WPB, THREADS>>>(vmem, labels, out);
}

// round 10
// speedup vs baseline: 1.4303x; 1.0549x over previous
#include <cuda_runtime.h>
#include <stdint.h>

// B=128, N=256, T=1024, C=10
#define T_LEN   1024
#define N_NEUR  256
#define C_GAP   10
#define WPB     8
#define THREADS (WPB * 32)
#define NEGINF  (-3.402823466e38f)
#define FULL    0xffffffffu
#define MAXCL   96
#define TILE_ROWS  8
#define TILE_BYTES (TILE_ROWS * T_LEN * 4)     // 32 KB
#define NBUF    2
#define SMEM_DYN (NBUF * TILE_BYTES)           // 64 KB
#define GRIDN   444                            // 3 blocks/SM * 148 SMs
#define NTILES  (128 * 256 / TILE_ROWS)        // 4096

__device__ float    g_loss;     // zero-init; reset by last block each launch
__device__ unsigned g_tick;

extern __shared__ float dbuf[];

__device__ __forceinline__ void mbar_wait(unsigned bar, int phase) {
    asm volatile(
        "{\n\t.reg .pred P;\n\t"
        "W%=:\n\t"
        "mbarrier.try_wait.parity.acquire.cta.shared::cta.b64 P, [%0], %1, 0x989680;\n\t"
        "@P bra.uni D%=;\n\t"
        "bra.uni W%=;\n\t"
        "D%=:\n\t}"
        :: "r"(bar), "r"(phase) : "memory");
}

__device__ __forceinline__ void issue_tile(unsigned dst, const float* src, unsigned bar) {
    asm volatile("mbarrier.arrive.expect_tx.shared.b64 _, [%0], %1;"
                 :: "r"(bar), "r"((unsigned)TILE_BYTES) : "memory");
    asm volatile("cp.async.bulk.shared::cluster.global.mbarrier::complete_tx::bytes "
                 "[%0], [%1], %2, [%3];"
                 :: "r"(dst), "l"(src), "r"((unsigned)TILE_BYTES), "r"(bar) : "memory");
}

// Process one row resident in smem at sbase. Result warp-uniform.
__device__ __forceinline__ float process_row(unsigned sbase, int row, int l,
                                             unsigned* shp, unsigned* shcl,
                                             const int*   __restrict__ labels,
                                             float*       __restrict__ out)
{
    const bool lane0 = (l == 0);

    // Sync-free nibble packing: bit (4k+j) <-> time 128k+4l+j
    float maxall = NEGINF;
    unsigned pack = 0;
    #pragma unroll
    for (int k = 0; k < 8; ++k) {
        float4 v;
        unsigned a = sbase + (unsigned)((k * 32 + l) * 16);
        asm volatile("ld.shared.v4.f32 {%0,%1,%2,%3}, [%4];"
                     : "=f"(v.x), "=f"(v.y), "=f"(v.z), "=f"(v.w) : "r"(a));
        maxall = fmaxf(maxall, fmaxf(fmaxf(v.x, v.y), fmaxf(v.z, v.w)));
        unsigned nib = (v.x >= 0.0f ? 1u : 0u)
                     | (v.y >= 0.0f ? 2u : 0u)
                     | (v.z >= 0.0f ? 4u : 0u)
                     | (v.w >= 0.0f ? 8u : 0u);
        pack |= nib << (4 * k);
    }
    shp[l] = pack;
    __syncwarp();

    // Window mask for window l (times [32l, 32l+32))
    unsigned m = 0;
    {
        const unsigned ksh = 4 * (l >> 2);
        const unsigned* src = &shp[8 * (l & 3)];
        #pragma unroll
        for (int i = 0; i < 8; ++i)
            m |= ((src[i] >> ksh) & 0xFu) << (4 * i);
    }

    // Cluster-start mask: spike with no spike in previous C steps
    unsigned prev = __shfl_up_sync(FULL, m, 1);
    if (lane0) prev = 0;
    unsigned long long A  = ((unsigned long long)m << 32) | prev;
    unsigned long long t1 = (A << 1) | (A << 2);          // shifts {1,2}
    unsigned long long t2 = t1 | (t1 << 2);               // {1..4}
    unsigned long long t3 = t2 | (t2 << 4);               // {1..8}
    unsigned long long sp = t3 | (t1 << 8);               // {1..10}
    unsigned starts = m & ~(unsigned)(sp >> 32);

    const int sc = __popc(starts);
    const int nc = __reduce_add_sync(FULL, sc);

    const int b_     = row >> 8;
    const int nn     = row & (N_NEUR - 1);
    const int target = (__ldg(labels + b_) == nn) ? 1 : 0;

    float contrib = 0.0f;
    if (nc > target) {                       // warp-uniform
        if (nc == 1) {
            #pragma unroll
            for (int d = 16; d > 0; d >>= 1)
                maxall = fmaxf(maxall, __shfl_xor_sync(FULL, maxall, d));
            contrib = maxall;                // single cluster: span max == row max
        } else {
            const int pc = __popc(m);
            int ipc = pc, isc = sc;
            #pragma unroll
            for (int d = 1; d < 32; d <<= 1) {
                int vp = __shfl_up_sync(FULL, ipc, d);
                int vs = __shfl_up_sync(FULL, isc, d);
                if (l >= d) { ipc += vp; isc += vs; }
            }
            const int excl  = ipc - pc;
            int c           = isc - sc;
            const int S_tot = __shfl_sync(FULL, ipc, 31);

            unsigned sm_ = starts;
            const int tb = l * 32;
            while (sm_) {
                int bit = __ffs(sm_) - 1;
                sm_ &= sm_ - 1;
                int sb = excl + __popc(m & ((1u << bit) - 1u));
                shcl[c] = ((unsigned)sb << 16) | (unsigned)(tb + bit);
                ++c;
            }
            if (lane0) shcl[nc] = ((unsigned)S_tot << 16) | (unsigned)T_LEN;
            __syncwarp();

            int best = 0x7fffffff;
            for (int c0 = l; c0 < nc; c0 += 32) {
                unsigned a  = shcl[c0];
                unsigned bn = shcl[c0 + 1];
                int size = (int)(bn >> 16) - (int)(a >> 16);
                best = min(best, (size << 7) | c0);
            }
            best = __reduce_min_sync(FULL, (unsigned)best);
            const int cstar = best & 127;
            const unsigned a  = shcl[cstar];
            const unsigned bn = shcl[cstar + 1];
            const int cb  = (int)(a  & 0xffffu);
            const int ceN = (int)(bn & 0xffffu);
            const unsigned width = (unsigned)(ceN - cb);

            // span max from the smem tile (still resident)
            float smax = NEGINF;
            const int ks = cb >> 7, ke = (ceN - 1) >> 7;
            for (int k = ks; k <= ke; ++k) {
                float4 v;
                unsigned aa = sbase + (unsigned)((k * 32 + l) * 16);
                asm volatile("ld.shared.v4.f32 {%0,%1,%2,%3}, [%4];"
                             : "=f"(v.x), "=f"(v.y), "=f"(v.z), "=f"(v.w) : "r"(aa));
                int t0 = k * 128 + 4 * l;
                if ((unsigned)(t0     - cb) < width) smax = fmaxf(smax, v.x);
                if ((unsigned)(t0 + 1 - cb) < width) smax = fmaxf(smax, v.y);
                if ((unsigned)(t0 + 2 - cb) < width) smax = fmaxf(smax, v.z);
                if ((unsigned)(t0 + 3 - cb) < width) smax = fmaxf(smax, v.w);
            }
            #pragma unroll
            for (int d = 16; d > 0; d >>= 1)
                smax = fmaxf(smax, __shfl_xor_sync(FULL, smax, d));
            contrib = smax;
        }
    } else if (nc == 0 && target) {
        #pragma unroll
        for (int d = 16; d > 0; d >>= 1)
            maxall = fmaxf(maxall, __shfl_xor_sync(FULL, maxall, d));
        contrib = -maxall;
    }

    if (lane0) out[1 + row] = (float)nc;     // spike_output
    return contrib;
}

__global__ __launch_bounds__(THREADS)
void stca_main(const float* __restrict__ vmem,
               const int*   __restrict__ labels,
               float*       __restrict__ out)
{
    __shared__ unsigned sh_p[WPB][32];
    __shared__ unsigned sh_cl[WPB][MAXCL];
    __shared__ float    warp_contrib[WPB];
    __shared__ alignas(8) unsigned long long mbar[NBUF];

    const int tid = threadIdx.x;
    const int w   = tid >> 5;
    const int l   = tid & 31;
    const int bid = blockIdx.x;

    const unsigned smem0 = (unsigned)__cvta_generic_to_shared(dbuf);
    unsigned baraddr[NBUF];
    #pragma unroll
    for (int i = 0; i < NBUF; ++i)
        baraddr[i] = (unsigned)__cvta_generic_to_shared(&mbar[i]);

    if (tid == 0) {
        asm volatile("mbarrier.init.shared.b64 [%0], 1;" :: "r"(baraddr[0]) : "memory");
        asm volatile("mbarrier.init.shared.b64 [%0], 1;" :: "r"(baraddr[1]) : "memory");
    }
    __syncthreads();
    asm volatile("fence.proxy.async.shared::cta;" ::: "memory");

    const int cnt = (NTILES - bid + GRIDN - 1) / GRIDN;    // tiles for this block

    // prologue: prefetch first two tiles
    if (tid == 0) {
        issue_tile(smem0, vmem + (size_t)bid * TILE_ROWS * T_LEN, baraddr[0]);
        if (cnt > 1)
            issue_tile(smem0 + TILE_BYTES,
                       vmem + (size_t)(bid + GRIDN) * TILE_ROWS * T_LEN, baraddr[1]);
    }

    int ph0 = 0, ph1 = 0;
    float lsum = 0.0f;

    for (int k = 0; k < cnt; ++k) {
        const int b    = k & 1;
        const int tile = bid + k * GRIDN;
        const unsigned sb = smem0 + (unsigned)b * TILE_BYTES;

        if (b == 0) { mbar_wait(baraddr[0], ph0); ph0 ^= 1; }
        else        { mbar_wait(baraddr[1], ph1); ph1 ^= 1; }

        lsum += process_row(sb + (unsigned)(w * T_LEN * 4),
                            tile * TILE_ROWS + w, l,
                            sh_p[w], sh_cl[w], labels, out);
        __syncthreads();                      // all warps done reading buffer b

        if (tid == 0 && k + 2 < cnt)
            issue_tile(sb, vmem + (size_t)(tile + 2 * GRIDN) * TILE_ROWS * T_LEN,
                       baraddr[b]);
    }

    if (l == 0) warp_contrib[w] = lsum;
    __syncthreads();

    // grid reduction: device accumulator + ticket (graph-replay safe)
    if (tid == 0) {
        float s = 0.0f;
        #pragma unroll
        for (int i = 0; i < WPB; ++i) s += warp_contrib[i];
        atomicAdd(&g_loss, s);
        __threadfence();
        unsigned t = atomicAdd(&g_tick, 1u);
        if (t == gridDim.x - 1) {            // last block: publish + reset
            __threadfence();
            out[0] = g_loss;
            g_loss = 0.0f;
            g_tick = 0u;
        }
    }
}

extern "C" void kernel_launch(void* const* d_in, const int* in_sizes, int n_in,
                              void* d_out, int out_size) {
    const float* vmem   = (const float*)d_in[0];   // [128,256,1024] f32
    // d_in[1] = vlastmem — unused by the reference forward; deliberately not read
    const int*   labels = (const int*)d_in[2];     // [128] i32
    float*       out    = (float*)d_out;           // [1 + 128*256] f32

    static bool attr_set = false;                  // host-side only
    if (!attr_set) {
        cudaFuncSetAttribute(stca_main, cudaFuncAttributeMaxDynamicSharedMemorySize, SMEM_DYN);
        attr_set = true;
    }
    stca_main<<<GRIDN, THREADS, SMEM_DYN>>>(vmem, labels, out);
}